// round 4
// baseline (speedup 1.0000x reference)
#include <cuda_runtime.h>
#include <cuda_bf16.h>

#define N_COLS   4096
#define N_TERMS  2048
#define COL4     1024          // float4 columns
#define NBLK     148           // <= SM count (B300:148, GB300:152) -> all resident
#define NTHR     512
#define P1_ROWS  14            // ceil(2047 / 148)
#define N_TILES  384           // 128 gens tiles + 256 tail tiles, 16 rows each

// ---- scratch (device globals; no allocation allowed) ----
__device__ float4   g_partial[NBLK * COL4];   // per-block partial |x| column sums (2.4 MB)
__device__ float4   g_scale4[COL4];           // per-column generator scale
__device__ float4   g_val4[COL4];             // per-column delta*0.5*crossf
__device__ int4     g_cross4[COL4];           // per-column crossing flag
__device__ int4     g_row4[COL4];             // per-column scatter target row (or -1)
__device__ unsigned g_cnt;                    // barrier arrive counter (returns to 0 each launch)
__device__ unsigned g_epoch;                  // barrier epoch (monotonic across launches)

// Grid-wide barrier: epoch-based, deterministic across graph replays.
// All NBLK blocks must be resident (guaranteed: 1 block/SM config).
__device__ __forceinline__ void grid_bar(unsigned target_epoch) {
    __syncthreads();
    if (threadIdx.x == 0) {
        __threadfence();                       // make this block's phase writes visible
        unsigned ticket = atomicAdd(&g_cnt, 1);
        if (ticket == NBLK - 1) {
            atomicExch(&g_cnt, 0);             // all arrived; reset for next barrier/launch
            __threadfence();
            atomicAdd(&g_epoch, 1);
        } else {
            while (*(volatile unsigned*)&g_epoch < target_epoch) { }
        }
    }
    __syncthreads();
}

__global__ __launch_bounds__(NTHR) void k_fused(const float* __restrict__ x,
                                                float* __restrict__ out) {
    __shared__ unsigned s_epoch0;
    __shared__ int s_wsum[16];
    const int t = threadIdx.x;
    const int b = blockIdx.x;

    if (t == 0) s_epoch0 = *(volatile unsigned*)&g_epoch;  // pre-launch epoch
    __syncthreads();
    const unsigned e0 = s_epoch0;

    const float4* x4 = (const float4*)x;
    float4*       o4 = (float4*)out;

    // ---------- Phase 1: partial |x| column sums over rows 1..2047 ----------
    {
        int r0 = 1 + b * P1_ROWS;
        float4 a0 = make_float4(0.f, 0.f, 0.f, 0.f);
        float4 a1 = make_float4(0.f, 0.f, 0.f, 0.f);
        #pragma unroll
        for (int r = 0; r < P1_ROWS; r++) {
            int row = r0 + r;
            if (row < N_TERMS) {
                float4 v0 = x4[(size_t)row * COL4 + t];
                float4 v1 = x4[(size_t)row * COL4 + t + 512];
                a0.x += fabsf(v0.x); a0.y += fabsf(v0.y);
                a0.z += fabsf(v0.z); a0.w += fabsf(v0.w);
                a1.x += fabsf(v1.x); a1.y += fabsf(v1.y);
                a1.z += fabsf(v1.z); a1.w += fabsf(v1.w);
            }
        }
        g_partial[b * COL4 + t]       = a0;
        g_partial[b * COL4 + t + 512] = a1;
    }
    grid_bar(e0 + 1);

    // ---------- Phase 2: per-column stats (blocks 0..7, one column/thread) ----------
    if (b < 8) {
        int col = b * 512 + t;                 // 0..4095
        const float* gp = (const float*)g_partial;
        float s = 0.f;
        #pragma unroll 4
        for (int k = 0; k < NBLK; k++)
            s += gp[k * N_COLS + col];

        float c     = x[col];                  // x[0] center row
        float upper = c + s;
        float lower = c - s;
        bool  cross = (lower * upper) < 0.f;
        bool  pos   = lower >= 0.f;
        float crossf = cross ? 1.f : 0.f;
        float posf   = pos   ? 1.f : 0.f;

        float denom = upper - lower;
        float ratio = (denom != 0.f) ? (upper / denom) : 0.5f;
        float lam   = posf + crossf * ratio;

        float delta  = fmaxf(-lam * lower, (1.f - lam) * upper);
        float center = (delta * 0.5f + lam * c) * crossf + c * posf;

        ((float*)g_scale4)[col] = lam * crossf + posf;
        ((float*)g_val4)[col]   = delta * 0.5f * crossf;
        ((int*)g_cross4)[col]   = cross ? 1 : 0;
        out[col] = center;
    }
    grid_bar(e0 + 2);

    // ---------- Phase 3: block 0 scans 4096 cross flags -> target rows ----------
    if (b == 0) {
        int lane = t & 31, wid = t >> 5;       // 16 warps
        int4 c0 = g_cross4[2 * t];
        int4 c1 = g_cross4[2 * t + 1];
        int tsum = c0.x + c0.y + c0.z + c0.w + c1.x + c1.y + c1.z + c1.w;

        int v = tsum;
        #pragma unroll
        for (int o = 1; o < 32; o <<= 1) {
            int n = __shfl_up_sync(0xffffffffu, v, o);
            if (lane >= o) v += n;
        }
        if (lane == 31) s_wsum[wid] = v;
        __syncthreads();
        if (wid == 0 && lane < 16) {
            int wv = s_wsum[lane];
            #pragma unroll
            for (int o = 1; o < 16; o <<= 1) {
                int n = __shfl_up_sync(0x0000ffffu, wv, o);
                if (lane >= o) wv += n;
            }
            s_wsum[lane] = wv;
        }
        __syncthreads();

        int r = ((wid > 0) ? s_wsum[wid - 1] : 0) + (v - tsum);
        int4 t0, t1;
        t0.x = c0.x ? (N_TERMS + r) : -1; r += c0.x;
        t0.y = c0.y ? (N_TERMS + r) : -1; r += c0.y;
        t0.z = c0.z ? (N_TERMS + r) : -1; r += c0.z;
        t0.w = c0.w ? (N_TERMS + r) : -1; r += c0.w;
        t1.x = c1.x ? (N_TERMS + r) : -1; r += c1.x;
        t1.y = c1.y ? (N_TERMS + r) : -1; r += c1.y;
        t1.z = c1.z ? (N_TERMS + r) : -1; r += c1.z;
        t1.w = c1.w ? (N_TERMS + r) : -1;
        g_row4[2 * t]     = t0;
        g_row4[2 * t + 1] = t1;
    }
    grid_bar(e0 + 3);

    // ---------- Phase 4: output tiles (gens rows 1..2047 + tail rows 2048..6143) ----------
    for (int tile = b; tile < N_TILES; tile += NBLK) {
        if (tile < 128) {
            int r0 = 1 + tile * 16;
            #pragma unroll
            for (int half = 0; half < 2; half++) {
                int c = t + half * 512;
                float4 sc = g_scale4[c];
                #pragma unroll
                for (int r = 0; r < 16; r++) {
                    int row = r0 + r;
                    if (row < N_TERMS) {
                        float4 v = x4[(size_t)row * COL4 + c];
                        v.x *= sc.x; v.y *= sc.y; v.z *= sc.z; v.w *= sc.w;
                        o4[(size_t)row * COL4 + c] = v;
                    }
                }
            }
        } else {
            int r0 = N_TERMS + (tile - 128) * 16;
            #pragma unroll
            for (int half = 0; half < 2; half++) {
                int c = t + half * 512;
                int4   tr  = g_row4[c];
                float4 val = g_val4[c];
                #pragma unroll
                for (int r = 0; r < 16; r++) {
                    int row = r0 + r;
                    float4 z = make_float4(0.f, 0.f, 0.f, 0.f);
                    if (tr.x == row) z.x = val.x;
                    if (tr.y == row) z.y = val.y;
                    if (tr.z == row) z.z = val.z;
                    if (tr.w == row) z.w = val.w;
                    o4[(size_t)row * COL4 + c] = z;
                }
            }
        }
    }
}

extern "C" void kernel_launch(void* const* d_in, const int* in_sizes, int n_in,
                              void* d_out, int out_size) {
    const float* x = (const float*)d_in[0];
    float* out     = (float*)d_out;
    k_fused<<<NBLK, NTHR>>>(x, out);
}

// round 5
// speedup vs baseline: 1.0664x; 1.0664x over previous
#include <cuda_runtime.h>
#include <cuda_bf16.h>

#define N_COLS   4096
#define N_TERMS  2048
#define COL4     1024              // float4 columns
#define ROW_BLOCKS 128
#define ROWS_PER   16

// ---- scratch (device globals; no allocation allowed) ----
__device__ float  g_partial[ROW_BLOCKS * N_COLS];   // 2 MB partial |x| column sums
__device__ float4 g_scale4[COL4];                   // per-column generator scale
__device__ float4 g_val4[COL4];                     // per-column delta*0.5*crossf
__device__ int4   g_cross4[COL4];                   // per-column crossing flag
__device__ int4   g_row4[COL4];                     // per-column scatter row (or -1)

// K1: partial column reduction of |x| over rows 1..2047
__global__ void k_abs_partial(const float* __restrict__ x) {
    int col4 = blockIdx.x * blockDim.x + threadIdx.x;   // 0..1023
    int rb   = blockIdx.y;
    int r0   = 1 + rb * ROWS_PER;
    const float4* x4 = (const float4*)x;
    float4 acc = make_float4(0.f, 0.f, 0.f, 0.f);
    #pragma unroll
    for (int r = 0; r < ROWS_PER; r++) {
        int row = r0 + r;
        if (row < N_TERMS) {
            float4 v = x4[(size_t)row * COL4 + col4];
            acc.x += fabsf(v.x);
            acc.y += fabsf(v.y);
            acc.z += fabsf(v.z);
            acc.w += fabsf(v.w);
        }
    }
    ((float4*)&g_partial[rb * N_COLS])[col4] = acc;
}

// K2: per-column stats; writes center row out[0]
__global__ void k_column_stats(const float* __restrict__ x, float* __restrict__ out) {
    int col = blockIdx.x * blockDim.x + threadIdx.x;    // 0..4095
    float s = 0.f;
    #pragma unroll 16
    for (int rb = 0; rb < ROW_BLOCKS; rb++)
        s += g_partial[rb * N_COLS + col];

    float c     = x[col];
    float upper = c + s;
    float lower = c - s;
    bool  cross = (lower * upper) < 0.f;
    bool  pos   = lower >= 0.f;
    float crossf = cross ? 1.f : 0.f;
    float posf   = pos   ? 1.f : 0.f;

    float denom = upper - lower;
    float ratio = (denom != 0.f) ? (upper / denom) : 0.5f;
    float lam   = posf + crossf * ratio;

    float delta  = fmaxf(-lam * lower, (1.f - lam) * upper);
    float center = (delta * 0.5f + lam * c) * crossf + c * posf;

    ((float*)g_scale4)[col] = lam * crossf + posf;
    ((float*)g_val4)[col]   = delta * 0.5f * crossf;
    ((int*)g_cross4)[col]   = cross ? 1 : 0;
    out[col] = center;
}

// K3: single-block exclusive scan of cross flags -> per-column target row (or -1)
__global__ void k_scan() {
    __shared__ int warp_sums[32];
    int t = threadIdx.x, lane = t & 31, wid = t >> 5;   // 1024 threads

    int4 cf = g_cross4[t];
    int tsum = cf.x + cf.y + cf.z + cf.w;

    int v = tsum;
    #pragma unroll
    for (int o = 1; o < 32; o <<= 1) {
        int n = __shfl_up_sync(0xffffffffu, v, o);
        if (lane >= o) v += n;
    }
    if (lane == 31) warp_sums[wid] = v;
    __syncthreads();
    if (wid == 0) {
        int wv = warp_sums[lane];
        #pragma unroll
        for (int o = 1; o < 32; o <<= 1) {
            int n = __shfl_up_sync(0xffffffffu, wv, o);
            if (lane >= o) wv += n;
        }
        warp_sums[lane] = wv;
    }
    __syncthreads();

    int r = ((wid > 0) ? warp_sums[wid - 1] : 0) + (v - tsum);
    int4 tr;
    tr.x = cf.x ? (N_TERMS + r) : -1; r += cf.x;
    tr.y = cf.y ? (N_TERMS + r) : -1; r += cf.y;
    tr.z = cf.z ? (N_TERMS + r) : -1; r += cf.z;
    tr.w = cf.w ? (N_TERMS + r) : -1;
    g_row4[t] = tr;
}

// KZ (side stream, no dependencies): zero tail rows 2048..6143 (64 MB)
__global__ void k_zero_tail(float* __restrict__ out) {
    float4* o4 = (float4*)out + (size_t)N_TERMS * COL4;
    const int total = N_COLS * COL4;                    // 4M float4
    int i0 = blockIdx.x * blockDim.x + threadIdx.x;
    int stride = gridDim.x * blockDim.x;
    const float4 z = make_float4(0.f, 0.f, 0.f, 0.f);
    for (int i = i0; i < total; i += stride)
        o4[i] = z;
}

// K4: gens rows 1..2047 (cy<128) + spread scatter into zeroed tail (cy==128)
__global__ void k_gens(const float* __restrict__ x, float* __restrict__ out) {
    int cy = blockIdx.y;
    if (cy < ROW_BLOCKS) {
        int col4 = blockIdx.x * blockDim.x + threadIdx.x;   // 0..1023
        const float4* x4 = (const float4*)x;
        float4* o4 = (float4*)out;
        float4 s = g_scale4[col4];
        int r0 = 1 + cy * ROWS_PER;
        #pragma unroll
        for (int r = 0; r < ROWS_PER; r++) {
            int row = r0 + r;
            if (row < N_TERMS) {
                float4 v = x4[(size_t)row * COL4 + col4];
                v.x *= s.x; v.y *= s.y; v.z *= s.z; v.w *= s.w;
                o4[(size_t)row * COL4 + col4] = v;
            }
        }
    } else {
        // scatter: 4 blocks x 256 threads x 4 columns = 4096 columns
        int i = blockIdx.x * blockDim.x + threadIdx.x;      // 0..1023
        int4   tr  = g_row4[i];
        float4 val = g_val4[i];
        int col = i * 4;
        if (tr.x >= 0) out[(size_t)tr.x * N_COLS + col + 0] = val.x;
        if (tr.y >= 0) out[(size_t)tr.y * N_COLS + col + 1] = val.y;
        if (tr.z >= 0) out[(size_t)tr.z * N_COLS + col + 2] = val.z;
        if (tr.w >= 0) out[(size_t)tr.w * N_COLS + col + 3] = val.w;
    }
}

extern "C" void kernel_launch(void* const* d_in, const int* in_sizes, int n_in,
                              void* d_out, int out_size) {
    const float* x = (const float*)d_in[0];
    float* out     = (float*)d_out;

    // One-time side stream + events (created on first, uncaptured, call).
    static cudaStream_t s1 = nullptr;
    static cudaEvent_t ev_fork = nullptr, ev_join = nullptr;
    if (!s1) {
        cudaStreamCreateWithFlags(&s1, cudaStreamNonBlocking);
        cudaEventCreateWithFlags(&ev_fork, cudaEventDisableTiming);
        cudaEventCreateWithFlags(&ev_join, cudaEventDisableTiming);
    }

    // Fork: tail zeroing runs concurrently with the reduction chain.
    cudaEventRecord(ev_fork, 0);
    cudaStreamWaitEvent(s1, ev_fork, 0);
    k_zero_tail<<<1024, 256, 0, s1>>>(out);
    cudaEventRecord(ev_join, s1);

    // Main chain.
    dim3 g1(COL4 / 256, ROW_BLOCKS);                    // (4, 128)
    k_abs_partial<<<g1, 256>>>(x);
    k_column_stats<<<N_COLS / 256, 256>>>(x, out);
    k_scan<<<1, 1024>>>();

    // Join: gens + scatter need the zeroed tail and the scan results.
    cudaStreamWaitEvent(0, ev_join, 0);
    dim3 g4(COL4 / 256, ROW_BLOCKS + 1);                // (4, 129)
    k_gens<<<g4, 256>>>(x, out);
}

// round 7
// speedup vs baseline: 1.3433x; 1.2597x over previous
#include <cuda_runtime.h>
#include <cuda_bf16.h>

#define N_COLS   4096
#define N_TERMS  2048
#define COL4     1024              // float4 columns
#define ROW_BLOCKS 128
#define ROWS_PER   16
#define K2_BLOCKS  16              // 16 blocks x 256 threads = 4096 columns

// ---- scratch (device globals; no allocation allowed) ----
__device__ float  g_partial[ROW_BLOCKS * N_COLS];   // 2 MB partial |x| column sums
__device__ float4 g_scale4[COL4];                   // per-column generator scale
__device__ float4 g_val4[COL4];                     // per-column delta*0.5*crossf
__device__ int4   g_cross4[COL4];                   // per-column crossing flag
__device__ int4   g_rank4[COL4];                    // per-column local rank within K2 block
__device__ int    g_bcount[K2_BLOCKS];              // crossings per K2 block

// K1 (fused): y<128 -> partial |x| column sums over 16-row chunk;
//             y>=128 -> zero tail rows 2048..6143 (no dependencies -> free overlap).
__global__ void k1_reduce_zero(const float* __restrict__ x, float* __restrict__ out) {
    int col4 = blockIdx.x * blockDim.x + threadIdx.x;   // 0..1023
    int cy   = blockIdx.y;                              // 0..383

    if (cy < ROW_BLOCKS) {
        const float4* x4 = (const float4*)x;
        int r0 = 1 + cy * ROWS_PER;
        float4 acc = make_float4(0.f, 0.f, 0.f, 0.f);
        #pragma unroll
        for (int r = 0; r < ROWS_PER; r++) {
            int row = r0 + r;
            if (row < N_TERMS) {
                float4 v = x4[(size_t)row * COL4 + col4];
                acc.x += fabsf(v.x);
                acc.y += fabsf(v.y);
                acc.z += fabsf(v.z);
                acc.w += fabsf(v.w);
            }
        }
        ((float4*)&g_partial[cy * N_COLS])[col4] = acc;
    } else {
        float4* o4 = (float4*)out;
        int r0 = N_TERMS + (cy - ROW_BLOCKS) * ROWS_PER;
        const float4 z = make_float4(0.f, 0.f, 0.f, 0.f);
        #pragma unroll
        for (int r = 0; r < ROWS_PER; r++)
            o4[(size_t)(r0 + r) * COL4 + col4] = z;
    }
}

// K2: per-column stats + center row + block-local scan of crossing flags.
// 16 blocks x 256 threads, one column per thread.
__global__ void k2_stats(const float* __restrict__ x, float* __restrict__ out) {
    __shared__ int s_wsum[8];
    int t   = threadIdx.x;                  // 0..255
    int b   = blockIdx.x;                   // 0..15
    int col = b * 256 + t;
    int lane = t & 31, wid = t >> 5;        // 8 warps

    float s = 0.f;
    #pragma unroll 16
    for (int rb = 0; rb < ROW_BLOCKS; rb++)
        s += g_partial[rb * N_COLS + col];

    float c     = x[col];                   // x[0] center row
    float upper = c + s;
    float lower = c - s;
    bool  cross = (lower * upper) < 0.f;
    bool  pos   = lower >= 0.f;
    float crossf = cross ? 1.f : 0.f;
    float posf   = pos   ? 1.f : 0.f;

    float denom = upper - lower;
    float ratio = (denom != 0.f) ? (upper / denom) : 0.5f;
    float lam   = posf + crossf * ratio;

    float delta  = fmaxf(-lam * lower, (1.f - lam) * upper);
    float center = (delta * 0.5f + lam * c) * crossf + c * posf;

    ((float*)g_scale4)[col] = lam * crossf + posf;
    ((float*)g_val4)[col]   = delta * 0.5f * crossf;
    ((int*)g_cross4)[col]   = cross ? 1 : 0;
    out[col] = center;

    // --- block-local exclusive scan of crossing flags -> rank ---
    int flag = cross ? 1 : 0;
    int v = flag;
    #pragma unroll
    for (int o = 1; o < 32; o <<= 1) {
        int n = __shfl_up_sync(0xffffffffu, v, o);
        if (lane >= o) v += n;
    }
    if (lane == 31) s_wsum[wid] = v;        // inclusive warp totals
    __syncthreads();
    if (t < 8) {
        int wv = s_wsum[t];
        #pragma unroll
        for (int o = 1; o < 8; o <<= 1) {
            int n = __shfl_up_sync(0x000000ffu, wv, o);
            if (t >= o) wv += n;
        }
        s_wsum[t] = wv;                     // inclusive scan of warp totals
        if (t == 7) g_bcount[b] = wv;       // block total
    }
    __syncthreads();

    int rank = (v - flag) + ((wid > 0) ? s_wsum[wid - 1] : 0);
    ((int*)g_rank4)[col] = rank;
}

// K3 (fused): y<128 -> gens rows 1..2047; y==128 -> scatter ~4096 vals into
// the pre-zeroed tail using global base (prefix of g_bcount) + local rank.
__global__ void k3_gens_scatter(const float* __restrict__ x, float* __restrict__ out) {
    int cy = blockIdx.y;
    if (cy < ROW_BLOCKS) {
        int col4 = blockIdx.x * blockDim.x + threadIdx.x;   // 0..1023
        const float4* x4 = (const float4*)x;
        float4* o4 = (float4*)out;
        float4 sc = g_scale4[col4];
        int r0 = 1 + cy * ROWS_PER;
        #pragma unroll
        for (int r = 0; r < ROWS_PER; r++) {
            int row = r0 + r;
            if (row < N_TERMS) {
                float4 v = x4[(size_t)row * COL4 + col4];
                v.x *= sc.x; v.y *= sc.y; v.z *= sc.z; v.w *= sc.w;
                o4[(size_t)row * COL4 + col4] = v;
            }
        }
    } else {
        // 4 x-blocks * 256 threads = 1024 threads, 4 consecutive columns each
        // (4 consecutive cols never straddle a 256-col K2 block).
        int i = blockIdx.x * blockDim.x + threadIdx.x;      // 0..1023
        int4   cf   = g_cross4[i];
        int4   rk   = g_rank4[i];
        float4 val  = g_val4[i];
        int blk = i >> 6;                                   // (4*i)/256
        int base = 0;
        #pragma unroll
        for (int k = 0; k < K2_BLOCKS; k++)
            base += (k < blk) ? g_bcount[k] : 0;

        int col = i * 4;
        if (cf.x) out[(size_t)(N_TERMS + base + rk.x) * N_COLS + col + 0] = val.x;
        if (cf.y) out[(size_t)(N_TERMS + base + rk.y) * N_COLS + col + 1] = val.y;
        if (cf.z) out[(size_t)(N_TERMS + base + rk.z) * N_COLS + col + 2] = val.z;
        if (cf.w) out[(size_t)(N_TERMS + base + rk.w) * N_COLS + col + 3] = val.w;
    }
}

extern "C" void kernel_launch(void* const* d_in, const int* in_sizes, int n_in,
                              void* d_out, int out_size) {
    const float* x = (const float*)d_in[0];
    float* out     = (float*)d_out;

    dim3 g1(COL4 / 256, ROW_BLOCKS + N_COLS / ROWS_PER); // (4, 384): reduce + zero tail
    k1_reduce_zero<<<g1, 256>>>(x, out);
    k2_stats<<<K2_BLOCKS, 256>>>(x, out);
    dim3 g3(COL4 / 256, ROW_BLOCKS + 1);                 // (4, 129): gens + scatter
    k3_gens_scatter<<<g3, 256>>>(x, out);
}